// round 5
// baseline (speedup 1.0000x reference)
#include <cuda_runtime.h>
#include <cuda_bf16.h>
#include <cstdint>

// Problem constants (fixed by the reference)
#define NQ      256      // number of queries (D)
#define KDIM    256      // descriptor dim (C)
#define DBP     257      // places_db row pitch in floats (256 dims + id)
#define NT      64       // db rows per tile (MMA N)
#define THREADS 256
#define MAXH    1024
#define MIN_SIM_F   0.8f
#define SCAN_THR    0.65f   // fp8 scan threshold: 0.8 - worst-case fp8 error bound (0.13) - margin
#define TOPK    10
#define GRID_SMS 152

// fp8 smem tiles, k-permuted layout, pitch 272 B (16*17: conflict-free, 16B-aligned rows)
#define FPITCH  272
#define A_OFF   0
#define A_BYTES (NQ * FPITCH)              // 69632
#define B_OFF   A_BYTES
#define B_BYTES (NT * FPITCH)              // 17408
#define SMEM_TOTAL (A_BYTES + B_BYTES)     // 87040

// Scratch (device globals — no allocations allowed)
__device__ int g_hitCnt[NQ];
__device__ int g_hitIdx[NQ * MAXH];

__global__ void init_kernel() {
    if (threadIdx.x < NQ) g_hitCnt[threadIdx.x] = 0;
}

// k-permuted byte offset: element (row, k) with k = 32*ks + 16*h + 4*q + r
// stored at row*FPITCH + q*64 + ks*8 + h*4 + r.
// => a thread's mma fragment bytes (fixed q = lane&3) are contiguous per row,
//    and one 16B LDS.128 covers two k-steps (a0,a2,a0',a2' / b0,b1,b0',b1').
__device__ __forceinline__ uint32_t poff(int row, int k) {
    return (uint32_t)(row * FPITCH + ((k >> 2) & 3) * 64 + (k >> 5) * 8 +
                      ((k >> 4) & 1) * 4 + (k & 3));
}

__device__ __forceinline__ uint16_t f2_e4m3x2(float hi, float lo) {
    uint16_t h;
    asm("cvt.rn.satfinite.e4m3x2.f32 %0, %1, %2;" : "=h"(h) : "f"(hi), "f"(lo));
    return h;
}

__device__ __forceinline__ void mma_e4m3(float* acc, const uint32_t a0, const uint32_t a1,
                                         const uint32_t a2, const uint32_t a3,
                                         const uint32_t b0, const uint32_t b1) {
    asm volatile(
        "mma.sync.aligned.m16n8k32.row.col.f32.e4m3.e4m3.f32 "
        "{%0,%1,%2,%3}, {%4,%5,%6,%7}, {%8,%9}, {%0,%1,%2,%3};\n"
        : "+f"(acc[0]), "+f"(acc[1]), "+f"(acc[2]), "+f"(acc[3])
        : "r"(a0), "r"(a1), "r"(a2), "r"(a3), "r"(b0), "r"(b1));
}

// ---------------------------------------------------------------------------
// FP8 mma.sync GEMM + threshold scan.
// C[256, N] = desc @ X^T; emit db indices with fp8-sim >= SCAN_THR (rare).
// ---------------------------------------------------------------------------
__global__ void __launch_bounds__(THREADS, 1)
gemm_scan_kernel(const float* __restrict__ desc,
                 const float* __restrict__ db,
                 int ndb, int ntiles)
{
    extern __shared__ __align__(16) unsigned char smem[];
    unsigned char* As = smem + A_OFF;
    unsigned char* Bs = smem + B_OFF;

    const int tid  = threadIdx.x;
    const int lane = tid & 31;
    const int warp = tid >> 5;
    const int wm   = warp & 3;   // M group: rows [wm*64, wm*64+64)
    const int wn   = warp >> 2;  // N group: cols [wn*32, wn*32+32)

    // ---- Convert A (descriptors, f32 -> e4m3, permuted layout) once ----
    {
        const float4* A4 = reinterpret_cast<const float4*>(desc);
        #pragma unroll 4
        for (int i = tid; i < (NQ * KDIM) / 4; i += THREADS) {
            float4 v = A4[i];
            int e = i * 4;
            int r = e >> 8;          // /256
            int c = e & 255;         // k, 4-aligned -> 4 contiguous bytes in perm layout
            uint16_t h0 = f2_e4m3x2(v.y, v.x);
            uint16_t h1 = f2_e4m3x2(v.w, v.z);
            uint32_t packed = (uint32_t)h0 | ((uint32_t)h1 << 16);
            *reinterpret_cast<uint32_t*>(As + poff(r, c)) = packed;
        }
    }

    // ---- Stage tile 0 (contiguous, aligned float4 stream) ----
    float4 st[17];
    int t = blockIdx.x;
    if (t < ntiles) {
        const float4* B4 = reinterpret_cast<const float4*>(db + (size_t)t * (NT * DBP));
        int nf4 = (min(NT, ndb - t * NT) * DBP) >> 2;
        #pragma unroll
        for (int it = 0; it < 17; it++) {
            int i = tid + it * THREADS;
            st[it] = (i < nf4) ? B4[i] : make_float4(0.f, 0.f, 0.f, 0.f);
        }
    }

    for (; t < ntiles; t += gridDim.x) {
        __syncthreads();  // all warps done reading Bs for the previous tile

        // 1) convert staged regs (tile t, f32) -> Bs (e4m3, permuted)
        #pragma unroll
        for (int it = 0; it < 17; it++) {
            int i = tid + it * THREADS;
            if (i < (NT * DBP) / 4) {
                int e = i * 4;
                int r = e / DBP;
                int c = e - r * DBP;
                float v[4] = { st[it].x, st[it].y, st[it].z, st[it].w };
                #pragma unroll
                for (int j = 0; j < 4; j++) {
                    if (c < KDIM) {
                        uint16_t h = f2_e4m3x2(v[j], v[j]);
                        Bs[poff(r, c)] = (unsigned char)(h & 0xFF);
                    }
                    if (++c == DBP) { c = 0; r++; }
                }
            }
        }
        __syncthreads();

        // 2) stage next tile (LDGs in flight across the whole compute phase)
        int nxt = t + gridDim.x;
        if (nxt < ntiles) {
            const float4* B4 = reinterpret_cast<const float4*>(db + (size_t)nxt * (NT * DBP));
            int nf4 = (min(NT, ndb - nxt * NT) * DBP) >> 2;
            #pragma unroll
            for (int it = 0; it < 17; it++) {
                int i = tid + it * THREADS;
                st[it] = (i < nf4) ? B4[i] : make_float4(0.f, 0.f, 0.f, 0.f);
            }
        }

        // 3) MMA compute: warp tile 64(M) x 32(N), k=256 in 8 k32-steps (4 LDS pairs)
        float acc[4][4][4];
        #pragma unroll
        for (int mi = 0; mi < 4; mi++)
            #pragma unroll
            for (int ni = 0; ni < 4; ni++)
                #pragma unroll
                for (int cc = 0; cc < 4; cc++) acc[mi][ni][cc] = 0.f;

        const unsigned char* Abase = As + (lane & 3) * 64;
        const unsigned char* Bbase = Bs + (lane & 3) * 64;
        const int arow = wm * 64 + (lane >> 2);
        const int brow = wn * 32 + (lane >> 2);

        #pragma unroll
        for (int kp = 0; kp < 4; kp++) {            // each kp = two k32-steps
            uint4 alo[4], ahi[4], bb[4];
            #pragma unroll
            for (int mi = 0; mi < 4; mi++) {
                const unsigned char* p = Abase + (arow + mi * 16) * FPITCH + kp * 16;
                alo[mi] = *reinterpret_cast<const uint4*>(p);
                ahi[mi] = *reinterpret_cast<const uint4*>(p + 8 * FPITCH);
            }
            #pragma unroll
            for (int ni = 0; ni < 4; ni++) {
                const unsigned char* p = Bbase + (brow + ni * 8) * FPITCH + kp * 16;
                bb[ni] = *reinterpret_cast<const uint4*>(p);
            }
            #pragma unroll
            for (int mi = 0; mi < 4; mi++)
                #pragma unroll
                for (int ni = 0; ni < 4; ni++) {
                    mma_e4m3(acc[mi][ni], alo[mi].x, ahi[mi].x, alo[mi].y, ahi[mi].y,
                             bb[ni].x, bb[ni].y);
                    mma_e4m3(acc[mi][ni], alo[mi].z, ahi[mi].z, alo[mi].w, ahi[mi].w,
                             bb[ni].z, bb[ni].w);
                }
        }

        // 4) Epilogue: max-tree; rare candidate append (exactness restored in finalize)
        float vmax = -1e30f;
        #pragma unroll
        for (int mi = 0; mi < 4; mi++)
            #pragma unroll
            for (int ni = 0; ni < 4; ni++)
                #pragma unroll
                for (int cc = 0; cc < 4; cc++) vmax = fmaxf(vmax, acc[mi][ni][cc]);

        if (vmax >= SCAN_THR) {
            const int row0 = t * NT;
            #pragma unroll
            for (int mi = 0; mi < 4; mi++)
                #pragma unroll
                for (int ni = 0; ni < 4; ni++)
                    #pragma unroll
                    for (int cc = 0; cc < 4; cc++) {
                        if (acc[mi][ni][cc] >= SCAN_THR) {
                            int m = wm * 64 + mi * 16 + (lane >> 2) + ((cc >> 1) << 3);
                            int n = row0 + wn * 32 + ni * 8 + ((lane & 3) << 1) + (cc & 1);
                            if (n < ndb) {
                                int pos = atomicAdd(&g_hitCnt[m], 1);
                                if (pos < MAXH) g_hitIdx[m * MAXH + pos] = n;
                            }
                        }
                    }
        }
    }
}

// ---------------------------------------------------------------------------
// Finalize: exact fp32 recompute of candidates, top-10 (sim desc, idx asc),
// voting, box removal, sim_scores, output assembly. One CTA, 256 threads.
// ---------------------------------------------------------------------------
__global__ void finalize_kernel(const float* __restrict__ boxes,
                                const float* __restrict__ desc,
                                const float* __restrict__ db,
                                float* __restrict__ out)
{
    const int d = threadIdx.x;  // one thread per query / box
    __shared__ float sx1[NQ], sy1[NQ], sx2[NQ], sy2[NQ], sarea[NQ];
    __shared__ int   slbl[NQ];

    // --- exact recompute + top-10 insertion (sim desc, db-index asc) ---
    float ts[TOPK];
    int   tn[TOPK];
    int cnt = g_hitCnt[d];
    if (cnt > MAXH) cnt = MAXH;
    int K = 0;
    for (int i = 0; i < cnt; i++) {
        int n = g_hitIdx[d * MAXH + i];
        // exact fp32 dot product
        float s = 0.f;
        const float* qa = desc + (size_t)d * KDIM;
        const float* xb = db + (size_t)n * DBP;
        for (int k = 0; k < KDIM; k++) s = fmaf(qa[k], xb[k], s);
        if (s < MIN_SIM_F) continue;
        int p = K;
        while (p > 0 && (s > ts[p - 1] || (s == ts[p - 1] && n < tn[p - 1]))) p--;
        if (p < TOPK) {
            int end = (K < TOPK) ? K : (TOPK - 1);
            for (int q = end; q > p; q--) { ts[q] = ts[q - 1]; tn[q] = tn[q - 1]; }
            ts[p] = s; tn[p] = n;
            if (K < TOPK) K++;
        }
    }

    // --- voting: max count; ties -> smallest class id ---
    int ids[TOPK];
    for (int kk = 0; kk < K; kk++)
        ids[kk] = (int)db[(size_t)tn[kk] * DBP + (DBP - 1)];
    int best_cnt = 0, best_id = 0x7fffffff;
    for (int kk = 0; kk < K; kk++) {
        int c = 0;
        for (int j = 0; j < K; j++) c += (ids[j] == ids[kk]);
        if (c > best_cnt || (c == best_cnt && ids[kk] < best_id)) {
            best_cnt = c; best_id = ids[kk];
        }
    }
    int label = (best_cnt > 0) ? best_id : -1;

    // --- box overlap removal ---
    float x1 = boxes[d * 4 + 0], y1 = boxes[d * 4 + 1];
    float x2 = boxes[d * 4 + 2], y2 = boxes[d * 4 + 3];
    float area = (x2 - x1) * (y2 - y1);
    sx1[d] = x1; sy1[d] = y1; sx2[d] = x2; sy2[d] = y2;
    sarea[d] = area; slbl[d] = label;
    __syncthreads();

    bool removed = false;
    if (label >= 0) {
        for (int j = 0; j < NQ; j++) {
            if (j == d || slbl[j] != label) continue;
            float ix1 = fmaxf(x1, sx1[j]);
            float iy1 = fmaxf(y1, sy1[j]);
            float ix2 = fminf(x2, sx2[j]);
            float iy2 = fminf(y2, sy2[j]);
            float inter = fmaxf(ix2 - ix1, 0.f) * fmaxf(iy2 - iy1, 0.f);
            float asmall = fminf(area, sarea[j]);
            float ov = (asmall > 0.f) ? (inter / asmall) : 0.f;
            // remove[d] <=> exists same-label overlapping j with area_j <= area_d
            if (ov >= 0.8f && sarea[j] <= area) removed = true;
        }
    }
    int result = removed ? -1 : label;

    // --- sim_scores ---
    float score = 0.f;
    for (int kk = 0; kk < K; kk++)
        if (ids[kk] == result) score = fmaxf(score, ts[kk]);

    // --- output: [final_boxes (1024)] [sim_scores (256)] [results (256)] ---
    for (int i = d; i < NQ * 4; i += NQ) out[i] = boxes[i];
    out[NQ * 4 + d] = score;
    out[NQ * 5 + d] = (float)result;
}

// ---------------------------------------------------------------------------
extern "C" void kernel_launch(void* const* d_in, const int* in_sizes, int n_in,
                              void* d_out, int out_size)
{
    const float* boxes = (const float*)d_in[0];
    const float* desc  = (const float*)d_in[1];
    const float* db    = (const float*)d_in[2];
    int db_elems = in_sizes[2];
    for (int i = 0; i < n_in; i++) {
        if (in_sizes[i] == NQ * 4)         boxes = (const float*)d_in[i];
        else if (in_sizes[i] == NQ * KDIM) desc  = (const float*)d_in[i];
        else                               { db = (const float*)d_in[i]; db_elems = in_sizes[i]; }
    }
    int ndb    = db_elems / DBP;
    int ntiles = (ndb + NT - 1) / NT;

    cudaFuncSetAttribute(gemm_scan_kernel,
                         cudaFuncAttributeMaxDynamicSharedMemorySize, SMEM_TOTAL);

    init_kernel<<<1, THREADS>>>();
    gemm_scan_kernel<<<GRID_SMS, THREADS, SMEM_TOTAL>>>(desc, db, ndb, ntiles);
    finalize_kernel<<<1, NQ>>>(boxes, desc, db, (float*)d_out);
    (void)out_size;
}

// round 6
// speedup vs baseline: 1.4723x; 1.4723x over previous
#include <cuda_runtime.h>
#include <cuda_bf16.h>
#include <cstdint>

// Problem constants (fixed by the reference)
#define NQ      256      // number of queries (D)
#define KDIM    256      // descriptor dim (C)
#define DBP     257      // places_db row pitch in floats (256 dims + id)
#define NT      64       // db rows per tile
#define THREADS 512
#define MAXH    1024
#define MIN_SIM_F 0.8f
#define SCAN_THR  0.78f  // bf16 scan threshold (error bound < 0.01 for unit rows)
#define TOPK    10
#define GRID_SMS 152

#define APITCH  264      // bf16 row pitch (264*2=528B = 132 words; 132%32=4 -> LDSM conflict-free)
#define BPITCH  264
#define A_BYTES (NQ * APITCH * 2)      // 135168
#define B_BYTES (NT * BPITCH * 2)      // 33792
#define SMEM_TOTAL (A_BYTES + B_BYTES) // 168960

// Scratch (device globals — no allocations allowed)
__device__ int g_hitCnt[NQ];
__device__ int g_hitIdx[NQ * MAXH];

__global__ void init_kernel() {
    if (threadIdx.x < NQ) g_hitCnt[threadIdx.x] = 0;
}

__device__ __forceinline__ uint32_t smem_u32(const void* p) {
    uint32_t a;
    asm("{ .reg .u64 t; cvta.to.shared.u64 t, %1; cvt.u32.u64 %0, t; }" : "=r"(a) : "l"(p));
    return a;
}

#define LDSM4(r0, r1, r2, r3, addr) \
    asm volatile("ldmatrix.sync.aligned.m8n8.x4.shared.b16 {%0,%1,%2,%3}, [%4];" \
        : "=r"(r0), "=r"(r1), "=r"(r2), "=r"(r3) : "r"(addr))

__device__ __forceinline__ void mma_bf16(float* acc, uint32_t a0, uint32_t a1,
                                         uint32_t a2, uint32_t a3,
                                         uint32_t b0, uint32_t b1) {
    asm volatile(
        "mma.sync.aligned.m16n8k16.row.col.f32.bf16.bf16.f32 "
        "{%0,%1,%2,%3}, {%4,%5,%6,%7}, {%8,%9}, {%0,%1,%2,%3};\n"
        : "+f"(acc[0]), "+f"(acc[1]), "+f"(acc[2]), "+f"(acc[3])
        : "r"(a0), "r"(a1), "r"(a2), "r"(a3), "r"(b0), "r"(b1));
}

// ---------------------------------------------------------------------------
// bf16 mma.sync GEMM + threshold scan. 512 threads, warp tile 32(M) x 32(N).
// ---------------------------------------------------------------------------
__global__ void __launch_bounds__(THREADS, 1)
gemm_scan_kernel(const float* __restrict__ desc,
                 const float* __restrict__ db,
                 int ndb, int ntiles)
{
    extern __shared__ __align__(16) unsigned char smem[];
    __nv_bfloat16* As = reinterpret_cast<__nv_bfloat16*>(smem);           // [NQ][APITCH]
    __nv_bfloat16* Bs = As + NQ * APITCH;                                 // [NT][BPITCH]

    const int tid  = threadIdx.x;
    const int lane = tid & 31;
    const int warp = tid >> 5;   // 0..15
    const int wm   = warp >> 1;  // 0..7  : M rows [wm*32, wm*32+32)
    const int wn   = warp & 1;   // 0..1  : N cols [wn*32, wn*32+32)

    // ---- Convert A (descriptors, f32 -> bf16 smem) once per CTA ----
    {
        const float4* A4 = reinterpret_cast<const float4*>(desc);
        #pragma unroll 4
        for (int i = tid; i < (NQ * KDIM) / 4; i += THREADS) {
            float4 v = A4[i];
            int e = i * 4;
            int r = e >> 8;
            int c = e & 255;
            __nv_bfloat162* p = reinterpret_cast<__nv_bfloat162*>(As + r * APITCH + c);
            p[0] = __floats2bfloat162_rn(v.x, v.y);
            p[1] = __floats2bfloat162_rn(v.z, v.w);
        }
    }

    // ---- Per-lane ldmatrix base addresses (byte offsets into smem) ----
    const uint32_t smem_base = smem_u32(smem);
    const uint32_t Bs_base   = smem_base + A_BYTES;
    const int g  = lane >> 3;      // ldmatrix address group 0..3
    const int lr = lane & 7;       // row within group
    // A x4 tile order: (m0-7,k0) (m8-15,k0) (m0-7,k8) (m8-15,k8)
    uint32_t a_addr[2];
    #pragma unroll
    for (int mi = 0; mi < 2; mi++)
        a_addr[mi] = smem_base +
            (uint32_t)(((wm * 32 + mi * 16 + (g & 1) * 8 + lr) * APITCH + (g >> 1) * 8) * 2);
    // B x4 tile order: (n0-7,k0) (n0-7,k8) (n8-15,k0) (n8-15,k8)
    uint32_t b_addr[2];
    #pragma unroll
    for (int h = 0; h < 2; h++)
        b_addr[h] = Bs_base +
            (uint32_t)(((wn * 32 + h * 16 + (g >> 1) * 8 + lr) * BPITCH + (g & 1) * 8) * 2);

    // ---- Stage tile 0 (contiguous float4 stream) ----
    float4 st[9];
    const int NF4 = (NT * DBP) / 4;   // 4112
    int t = blockIdx.x;
    if (t < ntiles) {
        const float4* B4 = reinterpret_cast<const float4*>(db + (size_t)t * (NT * DBP));
        int nf4 = (min(NT, ndb - t * NT) * DBP) >> 2;
        #pragma unroll
        for (int it = 0; it < 9; it++) {
            int i = tid + it * THREADS;
            st[it] = (i < nf4) ? B4[i] : make_float4(0.f, 0.f, 0.f, 0.f);
        }
    }

    for (; t < ntiles; t += gridDim.x) {
        __syncthreads();  // all warps done reading Bs for previous tile

        // 1) convert staged regs (tile t) -> Bs (bf16), handling 257-float pitch
        #pragma unroll
        for (int it = 0; it < 9; it++) {
            int i = tid + it * THREADS;
            if (i < NF4) {
                int e = i * 4;
                int r = e / DBP;
                int c = e - r * DBP;
                float v[4] = { st[it].x, st[it].y, st[it].z, st[it].w };
                #pragma unroll
                for (int j = 0; j < 4; j++) {
                    if (c < KDIM) Bs[r * BPITCH + c] = __float2bfloat16(v[j]);
                    if (++c == DBP) { c = 0; r++; }
                }
            }
        }
        __syncthreads();

        // 2) stage next tile (LDGs in flight across the whole compute phase)
        int nxt = t + gridDim.x;
        if (nxt < ntiles) {
            const float4* B4 = reinterpret_cast<const float4*>(db + (size_t)nxt * (NT * DBP));
            int nf4 = (min(NT, ndb - nxt * NT) * DBP) >> 2;
            #pragma unroll
            for (int it = 0; it < 9; it++) {
                int i = tid + it * THREADS;
                st[it] = (i < nf4) ? B4[i] : make_float4(0.f, 0.f, 0.f, 0.f);
            }
        }

        // 3) MMA compute: warp tile 32(M) x 32(N), K=256
        float acc[2][4][4];
        #pragma unroll
        for (int mi = 0; mi < 2; mi++)
            #pragma unroll
            for (int ni = 0; ni < 4; ni++)
                #pragma unroll
                for (int cc = 0; cc < 4; cc++) acc[mi][ni][cc] = 0.f;

        #pragma unroll
        for (int ks = 0; ks < 16; ks++) {
            const uint32_t koff = (uint32_t)(ks * 32);   // 16 bf16 = 32 bytes
            uint32_t a[2][4], bb[2][4];
            LDSM4(a[0][0], a[0][1], a[0][2], a[0][3], a_addr[0] + koff);
            LDSM4(a[1][0], a[1][1], a[1][2], a[1][3], a_addr[1] + koff);
            LDSM4(bb[0][0], bb[0][1], bb[0][2], bb[0][3], b_addr[0] + koff);
            LDSM4(bb[1][0], bb[1][1], bb[1][2], bb[1][3], b_addr[1] + koff);
            #pragma unroll
            for (int mi = 0; mi < 2; mi++) {
                mma_bf16(acc[mi][0], a[mi][0], a[mi][1], a[mi][2], a[mi][3], bb[0][0], bb[0][1]);
                mma_bf16(acc[mi][1], a[mi][0], a[mi][1], a[mi][2], a[mi][3], bb[0][2], bb[0][3]);
                mma_bf16(acc[mi][2], a[mi][0], a[mi][1], a[mi][2], a[mi][3], bb[1][0], bb[1][1]);
                mma_bf16(acc[mi][3], a[mi][0], a[mi][1], a[mi][2], a[mi][3], bb[1][2], bb[1][3]);
            }
        }

        // 4) Epilogue: max-tree; rare candidate append (exact recompute in finalize)
        float vmax = -1e30f;
        #pragma unroll
        for (int mi = 0; mi < 2; mi++)
            #pragma unroll
            for (int ni = 0; ni < 4; ni++)
                #pragma unroll
                for (int cc = 0; cc < 4; cc++) vmax = fmaxf(vmax, acc[mi][ni][cc]);

        if (vmax >= SCAN_THR) {
            const int row0 = t * NT;
            #pragma unroll
            for (int mi = 0; mi < 2; mi++)
                #pragma unroll
                for (int ni = 0; ni < 4; ni++)
                    #pragma unroll
                    for (int cc = 0; cc < 4; cc++) {
                        if (acc[mi][ni][cc] >= SCAN_THR) {
                            int m = wm * 32 + mi * 16 + (lane >> 2) + ((cc >> 1) << 3);
                            int n = row0 + wn * 32 + ni * 8 + ((lane & 3) << 1) + (cc & 1);
                            if (n < ndb) {
                                int pos = atomicAdd(&g_hitCnt[m], 1);
                                if (pos < MAXH) g_hitIdx[m * MAXH + pos] = n;
                            }
                        }
                    }
        }
    }
}

// ---------------------------------------------------------------------------
// Finalize: exact fp32 recompute of candidates, top-10 (sim desc, idx asc),
// voting, box removal, sim_scores, output assembly. One CTA, 256 threads.
// ---------------------------------------------------------------------------
__global__ void finalize_kernel(const float* __restrict__ boxes,
                                const float* __restrict__ desc,
                                const float* __restrict__ db,
                                float* __restrict__ out)
{
    const int d = threadIdx.x;  // one thread per query / box
    __shared__ float sx1[NQ], sy1[NQ], sx2[NQ], sy2[NQ], sarea[NQ];
    __shared__ int   slbl[NQ];

    // --- exact recompute + top-10 insertion (sim desc, db-index asc) ---
    float ts[TOPK];
    int   tn[TOPK];
    int cnt = g_hitCnt[d];
    if (cnt > MAXH) cnt = MAXH;
    int K = 0;
    for (int i = 0; i < cnt; i++) {
        int n = g_hitIdx[d * MAXH + i];
        float s = 0.f;
        const float* qa = desc + (size_t)d * KDIM;
        const float* xb = db + (size_t)n * DBP;
        for (int k = 0; k < KDIM; k++) s = fmaf(qa[k], xb[k], s);
        if (s < MIN_SIM_F) continue;
        int p = K;
        while (p > 0 && (s > ts[p - 1] || (s == ts[p - 1] && n < tn[p - 1]))) p--;
        if (p < TOPK) {
            int end = (K < TOPK) ? K : (TOPK - 1);
            for (int q = end; q > p; q--) { ts[q] = ts[q - 1]; tn[q] = tn[q - 1]; }
            ts[p] = s; tn[p] = n;
            if (K < TOPK) K++;
        }
    }

    // --- voting: max count; ties -> smallest class id ---
    int ids[TOPK];
    for (int kk = 0; kk < K; kk++)
        ids[kk] = (int)db[(size_t)tn[kk] * DBP + (DBP - 1)];
    int best_cnt = 0, best_id = 0x7fffffff;
    for (int kk = 0; kk < K; kk++) {
        int c = 0;
        for (int j = 0; j < K; j++) c += (ids[j] == ids[kk]);
        if (c > best_cnt || (c == best_cnt && ids[kk] < best_id)) {
            best_cnt = c; best_id = ids[kk];
        }
    }
    int label = (best_cnt > 0) ? best_id : -1;

    // --- box overlap removal ---
    float x1 = boxes[d * 4 + 0], y1 = boxes[d * 4 + 1];
    float x2 = boxes[d * 4 + 2], y2 = boxes[d * 4 + 3];
    float area = (x2 - x1) * (y2 - y1);
    sx1[d] = x1; sy1[d] = y1; sx2[d] = x2; sy2[d] = y2;
    sarea[d] = area; slbl[d] = label;
    __syncthreads();

    bool removed = false;
    if (label >= 0) {
        for (int j = 0; j < NQ; j++) {
            if (j == d || slbl[j] != label) continue;
            float ix1 = fmaxf(x1, sx1[j]);
            float iy1 = fmaxf(y1, sy1[j]);
            float ix2 = fminf(x2, sx2[j]);
            float iy2 = fminf(y2, sy2[j]);
            float inter = fmaxf(ix2 - ix1, 0.f) * fmaxf(iy2 - iy1, 0.f);
            float asmall = fminf(area, sarea[j]);
            float ov = (asmall > 0.f) ? (inter / asmall) : 0.f;
            if (ov >= 0.8f && sarea[j] <= area) removed = true;
        }
    }
    int result = removed ? -1 : label;

    float score = 0.f;
    for (int kk = 0; kk < K; kk++)
        if (ids[kk] == result) score = fmaxf(score, ts[kk]);

    for (int i = d; i < NQ * 4; i += NQ) out[i] = boxes[i];
    out[NQ * 4 + d] = score;
    out[NQ * 5 + d] = (float)result;
}

// ---------------------------------------------------------------------------
extern "C" void kernel_launch(void* const* d_in, const int* in_sizes, int n_in,
                              void* d_out, int out_size)
{
    const float* boxes = (const float*)d_in[0];
    const float* desc  = (const float*)d_in[1];
    const float* db    = (const float*)d_in[2];
    int db_elems = in_sizes[2];
    for (int i = 0; i < n_in; i++) {
        if (in_sizes[i] == NQ * 4)         boxes = (const float*)d_in[i];
        else if (in_sizes[i] == NQ * KDIM) desc  = (const float*)d_in[i];
        else                               { db = (const float*)d_in[i]; db_elems = in_sizes[i]; }
    }
    int ndb    = db_elems / DBP;
    int ntiles = (ndb + NT - 1) / NT;

    cudaFuncSetAttribute(gemm_scan_kernel,
                         cudaFuncAttributeMaxDynamicSharedMemorySize, SMEM_TOTAL);

    init_kernel<<<1, 256>>>();
    gemm_scan_kernel<<<GRID_SMS, THREADS, SMEM_TOTAL>>>(desc, db, ndb, ntiles);
    finalize_kernel<<<1, NQ>>>(boxes, desc, db, (float*)d_out);
    (void)out_size;
}